// round 14
// baseline (speedup 1.0000x reference)
#include <cuda_runtime.h>
#include <cuda_fp16.h>
#include <math.h>

#define W 160
#define H 160
#define D 160
#define NB 2
#define PLANE (H * W)              // 25600
#define VOL (D * H * W)            // 4096000
#define INV_SZ (1.0f / 125.0f)

// xy tile geometry
#define TX 32
#define TY 32
#define HX 36

// z sliding-pass decomposition
#define CHUNK 16
#define NCHUNK 10
#define NCOLP (160 * 160)
#define SLIDE_THREADS (NCOLP * NCHUNK)    // 256000

// 4-field pack: p0 = (F,M) batch0, p1 = (F,M) batch1
struct __align__(8) H4 { __half2 p0, p1; };

// Scratch (__device__ globals: allocation-free rule)
__device__ H4 g_t01[VOL];
__device__ H4 g_s1[VOL];
__device__ H4 g_s2[VOL];
__device__ H4 g_fm[VOL];
__device__ __half2 g_t2[VOL];
__device__ double g_acc;

__device__ __forceinline__ float frsqrt_approx(float x) {
    float y;
    asm("rsqrt.approx.f32 %0, %1;" : "=f"(y) : "f"(x));
    return y;
}
__device__ __forceinline__ int clampi(int v, int lo, int hi) {
    return v < lo ? lo : (v > hi ? hi : v);
}
__device__ __forceinline__ H4 h4add(H4 a, H4 b) {
    H4 r; r.p0 = __hadd2(a.p0, b.p0); r.p1 = __hadd2(a.p1, b.p1); return r;
}
__device__ __forceinline__ H4 h4sub(H4 a, H4 b) {
    H4 r; r.p0 = __hsub2(a.p0, b.p0); r.p1 = __hsub2(a.p1, b.p1); return r;
}
__device__ __forceinline__ float2 f2add(float2 a, float2 b) {
    return make_float2(a.x + b.x, a.y + b.y);
}
__device__ __forceinline__ float2 f2sub(float2 a, float2 b) {
    return make_float2(a.x - b.x, a.y - b.y);
}

__global__ void k_zero_acc() { g_acc = 0.0; }

// ---------------------------------------------------------------------------
// Loaders: operator()(j, own). j = batch-0 voxel index; batch-1 at j + VOL.
struct LoadRaw4 {   // raw (F,M) pairs; populates fm cache on owned evals
    const float* __restrict__ f;
    const float* __restrict__ m;
    H4* __restrict__ fm;
    __device__ __forceinline__ H4 operator()(int j, bool own) const {
        H4 r;
        r.p0 = __floats2half2_rn(f[j], m[j]);
        r.p1 = __floats2half2_rn(f[j + VOL], m[j + VOL]);
        if (own) fm[j] = r;
        return r;
    }
};
struct LoadG4 {     // (im - u)^2 per field
    const H4* __restrict__ fm;
    const H4* __restrict__ s1;
    __device__ __forceinline__ H4 operator()(int j, bool) const {
        H4 a = fm[j], u = s1[j], r;
        float2 v0 = __half22float2(a.p0), u0 = __half22float2(u.p0);
        float2 v1 = __half22float2(a.p1), u1 = __half22float2(u.p1);
        float d0x = v0.x - u0.x * INV_SZ, d0y = v0.y - u0.y * INV_SZ;
        float d1x = v1.x - u1.x * INV_SZ, d1y = v1.y - u1.y * INV_SZ;
        r.p0 = __floats2half2_rn(d0x * d0x, d0y * d0y);
        r.p1 = __floats2half2_rn(d1x * d1x, d1y * d1y);
        return r;
    }
};
struct LoadP4 {     // n_F * n_M per batch -> half2 (b0, b1)
    const H4* __restrict__ fm;
    const H4* __restrict__ s1;
    const H4* __restrict__ s2;
    __device__ __forceinline__ __half2 operator()(int j, bool) const {
        H4 a = fm[j], u = s1[j], v = s2[j];
        float2 a0 = __half22float2(a.p0), u0 = __half22float2(u.p0), v0 = __half22float2(v.p0);
        float2 a1 = __half22float2(a.p1), u1 = __half22float2(u.p1), v1 = __half22float2(v.p1);
        float pr0 = fmaxf((v0.x * INV_SZ) * (v0.y * INV_SZ), 1e-24f);
        float pr1 = fmaxf((v1.x * INV_SZ) * (v1.y * INV_SZ), 1e-24f);
        float p0 = (a0.x - u0.x * INV_SZ) * (a0.y - u0.y * INV_SZ) * frsqrt_approx(pr0);
        float p1 = (a1.x - u1.x * INV_SZ) * (a1.y - u1.y * INV_SZ) * frsqrt_approx(pr1);
        return __floats2half2_rn(p0, p1);
    }
};

// ---------------------------------------------------------------------------
// xy box, H4 fields. Phase A: direct-global y-slide (runs of 8, 12 evals,
// 5-deep rolling window) -> s_yr[y][x]. Phase B: x-slide (runs of 4).
// grid = (5, 5, D), block = 256.
template <class L>
__global__ void __launch_bounds__(256) k_xy_pair4(L ld, H4* __restrict__ out) {
    __shared__ H4 s_yr[TY][HX + 1];   // [y][x], row stride 37 (conflict-free)

    const int gx0 = blockIdx.x * TX;
    const int gy0 = blockIdx.y * TY;
    const int zbase = blockIdx.z * PLANE;
    const int tid = threadIdx.x;

    // Phase A: 36 halo columns x 4 y-runs of 8 = 144 tasks
    if (tid < HX * 4) {
        int x  = tid % HX;
        int yg = tid / HX;
        int y0 = yg * 8;
        int gx = clampi(gx0 - 2 + x, 0, W - 1);
        int gybase = gy0 + y0 - 2;

        H4 w0, w1, w2, w3, w4;
        w0 = ld(zbase + clampi(gybase + 0, 0, H - 1) * W + gx, false);
        w1 = ld(zbase + clampi(gybase + 1, 0, H - 1) * W + gx, false);
        w2 = ld(zbase + (gybase + 2) * W + gx, true);   // owned rows 2..9
        w3 = ld(zbase + (gybase + 3) * W + gx, true);
        w4 = ld(zbase + (gybase + 4) * W + gx, true);
        H4 s = h4add(h4add(h4add(h4add(w0, w1), w2), w3), w4);
        s_yr[y0][x] = s;
#pragma unroll
        for (int j = 1; j < 8; j++) {
            int r = 4 + j;
            bool own = (r <= 9);
            H4 nw = ld(zbase + clampi(gybase + r, 0, H - 1) * W + gx, own);
            s = h4add(s, h4sub(nw, w0));
            w0 = w1; w1 = w2; w2 = w3; w3 = w4; w4 = nw;
            s_yr[y0 + j][x] = s;
        }
    }
    __syncthreads();

    // Phase B: 32 rows x 8 x-runs of 4 = 256 tasks; conflict-free LDS.64
    {
        int xg = tid % 8;
        int yrow = tid / 8;
        int x0 = 4 * xg;
        H4 s = h4add(h4add(h4add(h4add(s_yr[yrow][x0], s_yr[yrow][x0 + 1]),
                                 s_yr[yrow][x0 + 2]), s_yr[yrow][x0 + 3]),
                     s_yr[yrow][x0 + 4]);
        __align__(16) H4 r[4];
        r[0] = s;
#pragma unroll
        for (int j = 1; j < 4; j++) {
            s = h4add(s, h4sub(s_yr[yrow][x0 + 4 + j], s_yr[yrow][x0 + j - 1]));
            r[j] = s;
        }
        int o = zbase + (gy0 + yrow) * W + gx0 + x0;
        *reinterpret_cast<uint4*>(&out[o])     = *reinterpret_cast<uint4*>(&r[0]);
        *reinterpret_cast<uint4*>(&out[o + 2]) = *reinterpret_cast<uint4*>(&r[2]);
    }
}

// Stage-3 xy kernel: half2 per voxel, same structure.
template <class L>
__global__ void __launch_bounds__(256) k_xy_one4(L ld, __half2* __restrict__ out) {
    __shared__ __half2 s_yr[TY][HX + 1];

    const int gx0 = blockIdx.x * TX;
    const int gy0 = blockIdx.y * TY;
    const int zbase = blockIdx.z * PLANE;
    const int tid = threadIdx.x;

    if (tid < HX * 4) {
        int x  = tid % HX;
        int yg = tid / HX;
        int y0 = yg * 8;
        int gx = clampi(gx0 - 2 + x, 0, W - 1);
        int gybase = gy0 + y0 - 2;

        __half2 w0, w1, w2, w3, w4;
        w0 = ld(zbase + clampi(gybase + 0, 0, H - 1) * W + gx, false);
        w1 = ld(zbase + clampi(gybase + 1, 0, H - 1) * W + gx, false);
        w2 = ld(zbase + (gybase + 2) * W + gx, false);
        w3 = ld(zbase + (gybase + 3) * W + gx, false);
        w4 = ld(zbase + (gybase + 4) * W + gx, false);
        __half2 s = __hadd2(__hadd2(__hadd2(__hadd2(w0, w1), w2), w3), w4);
        s_yr[y0][x] = s;
#pragma unroll
        for (int j = 1; j < 8; j++) {
            __half2 nw = ld(zbase + clampi(gybase + 4 + j, 0, H - 1) * W + gx, false);
            s = __hadd2(s, __hsub2(nw, w0));
            w0 = w1; w1 = w2; w2 = w3; w3 = w4; w4 = nw;
            s_yr[y0 + j][x] = s;
        }
    }
    __syncthreads();

    {
        int xg = tid % 8;
        int yrow = tid / 8;
        int x0 = 4 * xg;
        __half2 s = __hadd2(__hadd2(__hadd2(__hadd2(s_yr[yrow][x0], s_yr[yrow][x0 + 1]),
                                            s_yr[yrow][x0 + 2]), s_yr[yrow][x0 + 3]),
                            s_yr[yrow][x0 + 4]);
        __align__(16) __half2 r[4];
        r[0] = s;
#pragma unroll
        for (int j = 1; j < 4; j++) {
            s = __hadd2(s, __hsub2(s_yr[yrow][x0 + 4 + j], s_yr[yrow][x0 + j - 1]));
            r[j] = s;
        }
        int o = zbase + (gy0 + yrow) * W + gx0 + x0;
        *reinterpret_cast<uint4*>(&out[o]) = *reinterpret_cast<uint4*>(r);
    }
}

// ---------------------------------------------------------------------------
// z-axis sliding 5-tap clamped sum on H4 columns (4 fields), fp32 accumulate.
__global__ void k_slide4_z(const H4* __restrict__ a, H4* __restrict__ o) {
    int tid = blockIdx.x * blockDim.x + threadIdx.x;
    if (tid >= SLIDE_THREADS) return;
    int c = tid % NCOLP;
    int chunk = tid / NCOLP;
    int base = c;
    int z0 = chunk * CHUNK;

    float2 s0 = make_float2(0.f, 0.f), s1a = make_float2(0.f, 0.f);
#pragma unroll
    for (int d = -2; d <= 2; d++) {
        int zz = clampi(z0 + d, 0, 159);
        H4 v = a[base + zz * PLANE];
        s0 = f2add(s0, __half22float2(v.p0));
        s1a = f2add(s1a, __half22float2(v.p1));
    }
#pragma unroll 4
    for (int j = 0; j < CHUNK; j++) {
        int z = z0 + j;
        H4 w;
        w.p0 = __float22half2_rn(s0);
        w.p1 = __float22half2_rn(s1a);
        o[base + z * PLANE] = w;
        int zn = z + 3 > 159 ? 159 : z + 3;
        int zo = z - 2 < 0 ? 0 : z - 2;
        H4 vn = a[base + zn * PLANE];
        H4 vo = a[base + zo * PLANE];
        s0 = f2add(s0, f2sub(__half22float2(vn.p0), __half22float2(vo.p0)));
        s1a = f2add(s1a, f2sub(__half22float2(vn.p1), __half22float2(vo.p1)));
    }
}

// Final z-pass + masked -sum(cross^2) reduction; both batches per thread.
__global__ void k_slide_reduce4(const __half2* __restrict__ a,
                                const float* __restrict__ mask) {
    __shared__ double sdata[256];
    int tid = blockIdx.x * blockDim.x + threadIdx.x;
    double acc = 0.0;
    if (tid < SLIDE_THREADS) {
        int c = tid % NCOLP;
        int chunk = tid / NCOLP;
        int base = c;
        int z0 = chunk * CHUNK;

        float2 s = make_float2(0.f, 0.f);
#pragma unroll
        for (int d = -2; d <= 2; d++) {
            int zz = clampi(z0 + d, 0, 159);
            s = f2add(s, __half22float2(a[base + zz * PLANE]));
        }
#pragma unroll 4
        for (int j = 0; j < CHUNK; j++) {
            int z = z0 + j;
            int i = base + z * PLANE;
            acc += (double)(s.x * s.x * mask[i]) + (double)(s.y * s.y * mask[i + VOL]);
            int zn = z + 3 > 159 ? 159 : z + 3;
            int zo = z - 2 < 0 ? 0 : z - 2;
            s = f2add(s, f2sub(__half22float2(a[base + zn * PLANE]),
                               __half22float2(a[base + zo * PLANE])));
        }
    }
    int t = threadIdx.x;
    sdata[t] = acc;
    __syncthreads();
    for (int sft = 128; sft > 0; sft >>= 1) {
        if (t < sft) sdata[t] += sdata[t + sft];
        __syncthreads();
    }
    if (t == 0) atomicAdd(&g_acc, sdata[0]);
}

__global__ void k_finish(float* __restrict__ out) {
    out[0] = (float)(-g_acc);
}

// ---------------------------------------------------------------------------
extern "C" void kernel_launch(void* const* d_in, const int* in_sizes, int n_in,
                              void* d_out, int out_size) {
    const float* f    = (const float*)d_in[0];
    const float* m    = (const float*)d_in[1];
    const float* mask = (const float*)d_in[2];
    float* out = (float*)d_out;

    H4* t01 = nullptr; cudaGetSymbolAddress((void**)&t01, g_t01);
    H4* s1  = nullptr; cudaGetSymbolAddress((void**)&s1, g_s1);
    H4* s2  = nullptr; cudaGetSymbolAddress((void**)&s2, g_s2);
    H4* fm  = nullptr; cudaGetSymbolAddress((void**)&fm, g_fm);
    __half2* t2 = nullptr; cudaGetSymbolAddress((void**)&t2, g_t2);

    dim3 grd(W / TX, H / TY, D);        // (5, 5, 160)
    const int TB = 256;
    const int gridS = (SLIDE_THREADS + TB - 1) / TB;

    k_zero_acc<<<1, 1>>>();

    // Stage 1
    k_xy_pair4<<<grd, TB>>>(LoadRaw4{f, m, fm}, t01);
    k_slide4_z<<<gridS, TB>>>(t01, s1);

    // Stage 2
    k_xy_pair4<<<grd, TB>>>(LoadG4{fm, s1}, t01);
    k_slide4_z<<<gridS, TB>>>(t01, s2);

    // Stage 3
    k_xy_one4<<<grd, TB>>>(LoadP4{fm, s1, s2}, t2);
    k_slide_reduce4<<<gridS, TB>>>(t2, mask);

    k_finish<<<1, 1>>>(out);
    (void)in_sizes; (void)n_in; (void)out_size;
}

// round 15
// speedup vs baseline: 1.1442x; 1.1442x over previous
#include <cuda_runtime.h>
#include <cuda_fp16.h>
#include <math.h>

#define W 160
#define H 160
#define D 160
#define NB 2
#define PLANE (H * W)              // 25600
#define VOL (D * H * W)            // 4096000
#define INV_SZ (1.0f / 125.0f)

// xy tile geometry
#define TX 32
#define TY 32
#define HX 36
#define HY 36

// z sliding-pass decomposition
#define CHUNK 16
#define NCHUNK 10
#define NCOLP (160 * 160)
#define SLIDE_THREADS (NCOLP * NCHUNK)    // 256000

// 4-field pack: p0 = (F,M) batch0, p1 = (F,M) batch1
struct __align__(8) H4 { __half2 p0, p1; };

// Scratch (__device__ globals: allocation-free rule)
__device__ H4 g_t01[VOL];
__device__ H4 g_s1[VOL];
__device__ H4 g_s2[VOL];
__device__ H4 g_fm[VOL];
__device__ __half2 g_t2[VOL];
__device__ double g_acc;

__device__ __forceinline__ float frsqrt_approx(float x) {
    float y;
    asm("rsqrt.approx.f32 %0, %1;" : "=f"(y) : "f"(x));
    return y;
}
__device__ __forceinline__ int clampi(int v, int lo, int hi) {
    return v < lo ? lo : (v > hi ? hi : v);
}
__device__ __forceinline__ H4 h4add(H4 a, H4 b) {
    H4 r; r.p0 = __hadd2(a.p0, b.p0); r.p1 = __hadd2(a.p1, b.p1); return r;
}
__device__ __forceinline__ H4 h4sub(H4 a, H4 b) {
    H4 r; r.p0 = __hsub2(a.p0, b.p0); r.p1 = __hsub2(a.p1, b.p1); return r;
}
__device__ __forceinline__ float2 f2add(float2 a, float2 b) {
    return make_float2(a.x + b.x, a.y + b.y);
}
__device__ __forceinline__ float2 f2sub(float2 a, float2 b) {
    return make_float2(a.x - b.x, a.y - b.y);
}

__global__ void k_zero_acc() { g_acc = 0.0; }

// ---------------------------------------------------------------------------
// Loaders: j = batch-0 voxel index; batch-1 lives at j + VOL.
struct LoadRaw4 {   // raw (F,M) pairs; side effect: populate half fm cache
    const float* __restrict__ f;
    const float* __restrict__ m;
    H4* __restrict__ fm;
    __device__ __forceinline__ H4 operator()(int j) const {
        H4 r;
        r.p0 = __floats2half2_rn(f[j], m[j]);
        r.p1 = __floats2half2_rn(f[j + VOL], m[j + VOL]);
        fm[j] = r;  // duplicate same-value writes at halo overlaps are benign
        return r;
    }
};
struct LoadG4 {     // (im - u)^2 per field
    const H4* __restrict__ fm;
    const H4* __restrict__ s1;
    __device__ __forceinline__ H4 operator()(int j) const {
        H4 a = fm[j], u = s1[j], r;
        float2 v0 = __half22float2(a.p0), u0 = __half22float2(u.p0);
        float2 v1 = __half22float2(a.p1), u1 = __half22float2(u.p1);
        float d0x = v0.x - u0.x * INV_SZ, d0y = v0.y - u0.y * INV_SZ;
        float d1x = v1.x - u1.x * INV_SZ, d1y = v1.y - u1.y * INV_SZ;
        r.p0 = __floats2half2_rn(d0x * d0x, d0y * d0y);
        r.p1 = __floats2half2_rn(d1x * d1x, d1y * d1y);
        return r;
    }
};
struct LoadP4 {     // n_F * n_M per batch -> half2 (b0, b1)
    const H4* __restrict__ fm;
    const H4* __restrict__ s1;
    const H4* __restrict__ s2;
    __device__ __forceinline__ __half2 operator()(int j) const {
        H4 a = fm[j], u = s1[j], v = s2[j];
        float2 a0 = __half22float2(a.p0), u0 = __half22float2(u.p0), v0 = __half22float2(v.p0);
        float2 a1 = __half22float2(a.p1), u1 = __half22float2(u.p1), v1 = __half22float2(v.p1);
        float pr0 = fmaxf((v0.x * INV_SZ) * (v0.y * INV_SZ), 1e-24f);
        float pr1 = fmaxf((v1.x * INV_SZ) * (v1.y * INV_SZ), 1e-24f);
        float p0 = (a0.x - u0.x * INV_SZ) * (a0.y - u0.y * INV_SZ) * frsqrt_approx(pr0);
        float p1 = (a1.x - u1.x * INV_SZ) * (a1.y - u1.y * INV_SZ) * frsqrt_approx(pr1);
        return __floats2half2_rn(p0, p1);
    }
};

// ---------------------------------------------------------------------------
// xy box of one 32x32 tile of one z-plane, 4 fields packed.
// Halo load: 256-thread coalesced (R13). Phases A/B: register-window slides,
// runs of 8 (12 smem reads per 8 outputs instead of 22).
// grid = (5, 5, D) = 4000 blocks, block = 256.
template <class L>
__global__ void __launch_bounds__(256) k_xy_pair4(L ld, H4* __restrict__ out) {
    __shared__ H4 s_in[HY][HX + 1];   // [halo y][halo x]
    __shared__ H4 s_yr[TY][HX + 1];   // [out y][halo x]

    const int gx0 = blockIdx.x * TX;
    const int gy0 = blockIdx.y * TY;
    const int zbase = blockIdx.z * PLANE;
    const int tid = threadIdx.x;

    // Halo load (replicate padding via clamped coords), full block, coalesced.
    for (int i = tid; i < HY * HX; i += 256) {
        int ly = i / HX;
        int lx = i - ly * HX;
        int gy = clampi(gy0 - 2 + ly, 0, H - 1);
        int gx = clampi(gx0 - 2 + lx, 0, W - 1);
        s_in[ly][lx] = ld(zbase + gy * W + gx);
    }
    __syncthreads();

    // Phase A: y-box, 36 cols x 4 runs of 8 = 144 tasks, register window.
    if (tid < HX * 4) {
        int x  = tid % HX;
        int y0 = (tid / HX) * 8;
        H4 w0 = s_in[y0][x], w1 = s_in[y0 + 1][x], w2 = s_in[y0 + 2][x];
        H4 w3 = s_in[y0 + 3][x], w4 = s_in[y0 + 4][x];
        H4 s = h4add(h4add(h4add(h4add(w0, w1), w2), w3), w4);
        s_yr[y0][x] = s;
#pragma unroll
        for (int j = 1; j < 8; j++) {
            H4 nw = s_in[y0 + 4 + j][x];
            s = h4add(s, h4sub(nw, w0));
            w0 = w1; w1 = w2; w2 = w3; w3 = w4; w4 = nw;
            s_yr[y0 + j][x] = s;
        }
    }
    __syncthreads();

    // Phase B: x-box, 32 rows x 4 runs of 8 = 128 tasks, register window.
    if (tid < TY * 4) {
        int xg = tid % 4;
        int yrow = tid / 4;
        int x0 = 8 * xg;
        H4 w0 = s_yr[yrow][x0], w1 = s_yr[yrow][x0 + 1], w2 = s_yr[yrow][x0 + 2];
        H4 w3 = s_yr[yrow][x0 + 3], w4 = s_yr[yrow][x0 + 4];
        __align__(16) H4 r[8];
        H4 s = h4add(h4add(h4add(h4add(w0, w1), w2), w3), w4);
        r[0] = s;
#pragma unroll
        for (int j = 1; j < 8; j++) {
            H4 nw = s_yr[yrow][x0 + 4 + j];
            s = h4add(s, h4sub(nw, w0));
            w0 = w1; w1 = w2; w2 = w3; w3 = w4; w4 = nw;
            r[j] = s;
        }
        int o = zbase + (gy0 + yrow) * W + gx0 + x0;
#pragma unroll
        for (int q = 0; q < 4; q++)
            *reinterpret_cast<uint4*>(&out[o + 2 * q]) = *reinterpret_cast<uint4*>(&r[2 * q]);
    }
}

// Stage-3 xy kernel: half2 (batch pair) per voxel, same structure.
template <class L>
__global__ void __launch_bounds__(256) k_xy_one4(L ld, __half2* __restrict__ out) {
    __shared__ __half2 s_in[HY][HX + 1];
    __shared__ __half2 s_yr[TY][HX + 1];

    const int gx0 = blockIdx.x * TX;
    const int gy0 = blockIdx.y * TY;
    const int zbase = blockIdx.z * PLANE;
    const int tid = threadIdx.x;

    for (int i = tid; i < HY * HX; i += 256) {
        int ly = i / HX;
        int lx = i - ly * HX;
        int gy = clampi(gy0 - 2 + ly, 0, H - 1);
        int gx = clampi(gx0 - 2 + lx, 0, W - 1);
        s_in[ly][lx] = ld(zbase + gy * W + gx);
    }
    __syncthreads();

    if (tid < HX * 4) {
        int x  = tid % HX;
        int y0 = (tid / HX) * 8;
        __half2 w0 = s_in[y0][x], w1 = s_in[y0 + 1][x], w2 = s_in[y0 + 2][x];
        __half2 w3 = s_in[y0 + 3][x], w4 = s_in[y0 + 4][x];
        __half2 s = __hadd2(__hadd2(__hadd2(__hadd2(w0, w1), w2), w3), w4);
        s_yr[y0][x] = s;
#pragma unroll
        for (int j = 1; j < 8; j++) {
            __half2 nw = s_in[y0 + 4 + j][x];
            s = __hadd2(s, __hsub2(nw, w0));
            w0 = w1; w1 = w2; w2 = w3; w3 = w4; w4 = nw;
            s_yr[y0 + j][x] = s;
        }
    }
    __syncthreads();

    if (tid < TY * 4) {
        int xg = tid % 4;
        int yrow = tid / 4;
        int x0 = 8 * xg;
        __half2 w0 = s_yr[yrow][x0], w1 = s_yr[yrow][x0 + 1], w2 = s_yr[yrow][x0 + 2];
        __half2 w3 = s_yr[yrow][x0 + 3], w4 = s_yr[yrow][x0 + 4];
        __align__(16) __half2 r[8];
        __half2 s = __hadd2(__hadd2(__hadd2(__hadd2(w0, w1), w2), w3), w4);
        r[0] = s;
#pragma unroll
        for (int j = 1; j < 8; j++) {
            __half2 nw = s_yr[yrow][x0 + 4 + j];
            s = __hadd2(s, __hsub2(nw, w0));
            w0 = w1; w1 = w2; w2 = w3; w3 = w4; w4 = nw;
            r[j] = s;
        }
        int o = zbase + (gy0 + yrow) * W + gx0 + x0;
        *reinterpret_cast<uint4*>(&out[o])     = *reinterpret_cast<uint4*>(&r[0]);
        *reinterpret_cast<uint4*>(&out[o + 4]) = *reinterpret_cast<uint4*>(&r[4]);
    }
}

// ---------------------------------------------------------------------------
// z-axis sliding 5-tap clamped sum on H4 columns (4 fields), fp32 accumulate.
__global__ void k_slide4_z(const H4* __restrict__ a, H4* __restrict__ o) {
    int tid = blockIdx.x * blockDim.x + threadIdx.x;
    if (tid >= SLIDE_THREADS) return;
    int c = tid % NCOLP;
    int chunk = tid / NCOLP;
    int base = c;
    int z0 = chunk * CHUNK;

    float2 s0 = make_float2(0.f, 0.f), s1a = make_float2(0.f, 0.f);
#pragma unroll
    for (int d = -2; d <= 2; d++) {
        int zz = clampi(z0 + d, 0, 159);
        H4 v = a[base + zz * PLANE];
        s0 = f2add(s0, __half22float2(v.p0));
        s1a = f2add(s1a, __half22float2(v.p1));
    }
#pragma unroll 4
    for (int j = 0; j < CHUNK; j++) {
        int z = z0 + j;
        H4 w;
        w.p0 = __float22half2_rn(s0);
        w.p1 = __float22half2_rn(s1a);
        o[base + z * PLANE] = w;
        int zn = z + 3 > 159 ? 159 : z + 3;
        int zo = z - 2 < 0 ? 0 : z - 2;
        H4 vn = a[base + zn * PLANE];
        H4 vo = a[base + zo * PLANE];
        s0 = f2add(s0, f2sub(__half22float2(vn.p0), __half22float2(vo.p0)));
        s1a = f2add(s1a, f2sub(__half22float2(vn.p1), __half22float2(vo.p1)));
    }
}

// Final z-pass + masked -sum(cross^2) reduction; both batches per thread.
__global__ void k_slide_reduce4(const __half2* __restrict__ a,
                                const float* __restrict__ mask) {
    __shared__ double sdata[256];
    int tid = blockIdx.x * blockDim.x + threadIdx.x;
    double acc = 0.0;
    if (tid < SLIDE_THREADS) {
        int c = tid % NCOLP;
        int chunk = tid / NCOLP;
        int base = c;
        int z0 = chunk * CHUNK;

        float2 s = make_float2(0.f, 0.f);
#pragma unroll
        for (int d = -2; d <= 2; d++) {
            int zz = clampi(z0 + d, 0, 159);
            s = f2add(s, __half22float2(a[base + zz * PLANE]));
        }
#pragma unroll 4
        for (int j = 0; j < CHUNK; j++) {
            int z = z0 + j;
            int i = base + z * PLANE;
            acc += (double)(s.x * s.x * mask[i]) + (double)(s.y * s.y * mask[i + VOL]);
            int zn = z + 3 > 159 ? 159 : z + 3;
            int zo = z - 2 < 0 ? 0 : z - 2;
            s = f2add(s, f2sub(__half22float2(a[base + zn * PLANE]),
                               __half22float2(a[base + zo * PLANE])));
        }
    }
    int t = threadIdx.x;
    sdata[t] = acc;
    __syncthreads();
    for (int sft = 128; sft > 0; sft >>= 1) {
        if (t < sft) sdata[t] += sdata[t + sft];
        __syncthreads();
    }
    if (t == 0) atomicAdd(&g_acc, sdata[0]);
}

__global__ void k_finish(float* __restrict__ out) {
    out[0] = (float)(-g_acc);
}

// ---------------------------------------------------------------------------
extern "C" void kernel_launch(void* const* d_in, const int* in_sizes, int n_in,
                              void* d_out, int out_size) {
    const float* f    = (const float*)d_in[0];
    const float* m    = (const float*)d_in[1];
    const float* mask = (const float*)d_in[2];
    float* out = (float*)d_out;

    H4* t01 = nullptr; cudaGetSymbolAddress((void**)&t01, g_t01);
    H4* s1  = nullptr; cudaGetSymbolAddress((void**)&s1, g_s1);
    H4* s2  = nullptr; cudaGetSymbolAddress((void**)&s2, g_s2);
    H4* fm  = nullptr; cudaGetSymbolAddress((void**)&fm, g_fm);
    __half2* t2 = nullptr; cudaGetSymbolAddress((void**)&t2, g_t2);

    dim3 grd(W / TX, H / TY, D);        // (5, 5, 160) = 4000 blocks
    const int TB = 256;
    const int gridS = (SLIDE_THREADS + TB - 1) / TB; // 1000

    k_zero_acc<<<1, 1>>>();

    // Stage 1: xy box of raw pairs (fills fm cache), z slide -> s1
    k_xy_pair4<<<grd, TB>>>(LoadRaw4{f, m, fm}, t01);
    k_slide4_z<<<gridS, TB>>>(t01, s1);

    // Stage 2: xy box of (im-u)^2 pairs, z slide -> s2
    k_xy_pair4<<<grd, TB>>>(LoadG4{fm, s1}, t01);
    k_slide4_z<<<gridS, TB>>>(t01, s2);

    // Stage 3: xy box of n_F*n_M (batch pair), z slide + masked reduction
    k_xy_one4<<<grd, TB>>>(LoadP4{fm, s1, s2}, t2);
    k_slide_reduce4<<<gridS, TB>>>(t2, mask);

    k_finish<<<1, 1>>>(out);
    (void)in_sizes; (void)n_in; (void)out_size;
}